// round 2
// baseline (speedup 1.0000x reference)
#include <cuda_runtime.h>
#include <cstdint>

static constexpr int E_EDGES = 250000;
static constexpr int T_E     = 16;                 // edges per warp tile
static constexpr int NTILE   = E_EDGES / T_E;      // 15625 (exact)

#define SQ3f  1.7320508075688772f
#define SQ5f  2.2360679774997896f
#define SQ15f 3.8729833462074170f
#define HSQ3f 0.8660254037844386f

typedef unsigned long long u64;

__device__ __forceinline__ u64 pack2(float a, float b) {
    u64 r; asm("mov.b64 %0, {%1, %2};" : "=l"(r) : "f"(a), "f"(b)); return r;
}
__device__ __forceinline__ float2 unpk(u64 v) {
    float2 r; asm("mov.b64 {%0, %1}, %2;" : "=f"(r.x), "=f"(r.y) : "l"(v)); return r;
}
__device__ __forceinline__ void fma2(u64& d, u64 a, u64 b) {
    asm("fma.rn.f32x2 %0, %1, %2, %0;" : "+l"(d) : "l"(a), "l"(b));
}

// Shared memory per block (128 threads = 4 warps):
//   WaS : float4[64][32]  (i0,i1 channel-pairs)      32 KB
//   WbS : float2[64][32]  (i2 channel-pair)          16 KB
//   stage: 4 warps x 2 edges x 608 floats            19 KB
static constexpr int WA_ELEMS       = 64 * 32;
static constexpr int STAGE_PER_WARP = 2 * 608;      // floats (19-float rows x 32 lanes, padded)
static constexpr int SMEM_BYTES     = WA_ELEMS * 16 + WA_ELEMS * 8 + 4 * STAGE_PER_WARP * 4; // 68608

__global__ void __launch_bounds__(128, 3)
sh_embed_kernel(const float* __restrict__ edge_vec,
                const float* __restrict__ inv_g,
                const float* __restrict__ Wg,
                float* __restrict__ out)
{
    extern __shared__ char smem[];
    float4* WaS       = (float4*)smem;
    float2* WbS       = (float2*)(smem + WA_ELEMS * 16);
    float*  stage_all = (float*) (smem + WA_ELEMS * 16 + WA_ELEMS * 8);

    const int tid  = threadIdx.x;
    const int lane = tid & 31;
    const int wid  = tid >> 5;
    float* stage = stage_all + wid * STAGE_PER_WARP;

    // ---- repack W into per-lane channel-pair layout ----
    // lane cp owns channels c0=2cp, c1=2cp+1.
    // W_lin[d, c*3 + i] : WaS[d][cp] = (W[d,6cp], W[d,6cp+3], W[d,6cp+1], W[d,6cp+4])
    //                     WbS[d][cp] = (W[d,6cp+2], W[d,6cp+5])
    for (int t = tid; t < WA_ELEMS; t += 128) {
        int cp = t & 31, d = t >> 5;
        const float* wr = Wg + d * 192 + cp * 6;
        WaS[t] = make_float4(wr[0], wr[3], wr[1], wr[4]);
        WbS[t] = make_float2(wr[2], wr[5]);
    }
    __syncthreads();

    const int warpsTotal = gridDim.x * 4;
    #pragma unroll 1
    for (int tile = blockIdx.x * 4 + wid; tile < NTILE; tile += warpsTotal) {
        const int eBase = tile * T_E;
        const float* invBase = inv_g + (size_t)eBase * 64;

        // accumulators: per edge, f32x2 over (c0,c1), one per irrep
        u64 a0[T_E], a1[T_E], a2[T_E];
        #pragma unroll
        for (int e = 0; e < T_E; e++) { a0[e] = 0; a1[e] = 0; a2[e] = 0; }

        // ---- GEMM: w[e, c, i] = sum_d inv[e,d] * W[d, c*3+i] ----
        #pragma unroll 1
        for (int d4 = 0; d4 < 16; ++d4) {
            // load 4 d-rows of this lane's W columns (per-lane distinct, full-width LDS)
            u64 A0[4], A1[4], A2[4];
            #pragma unroll
            for (int dd = 0; dd < 4; ++dd) {
                float4 wa = WaS[(d4 * 4 + dd) * 32 + lane];
                float2 wb = WbS[(d4 * 4 + dd) * 32 + lane];
                A0[dd] = pack2(wa.x, wa.y);
                A1[dd] = pack2(wa.z, wa.w);
                A2[dd] = pack2(wb.x, wb.y);
            }
            #pragma unroll
            for (int e = 0; e < T_E; e++) {
                // warp-uniform LDG.128 broadcast: 1 wavefront
                float4 iv = *(const float4*)(invBase + e * 64 + d4 * 4);
                u64 i0 = pack2(iv.x, iv.x);
                u64 i1 = pack2(iv.y, iv.y);
                u64 i2 = pack2(iv.z, iv.z);
                u64 i3 = pack2(iv.w, iv.w);
                fma2(a0[e], i0, A0[0]); fma2(a1[e], i0, A1[0]); fma2(a2[e], i0, A2[0]);
                fma2(a0[e], i1, A0[1]); fma2(a1[e], i1, A1[1]); fma2(a2[e], i1, A2[1]);
                fma2(a0[e], i2, A0[2]); fma2(a1[e], i2, A1[2]); fma2(a2[e], i2, A2[2]);
                fma2(a0[e], i3, A0[3]); fma2(a1[e], i3, A1[3]); fma2(a2[e], i3, A2[3]);
            }
        }

        // ---- epilogue: SH outer product + transpose-through-smem, 2 edges per pass ----
        #pragma unroll 1
        for (int ep = 0; ep < T_E; ep += 2) {
            #pragma unroll
            for (int s = 0; s < 2; ++s) {
                const int e = ep + s;
                // warp-uniform edge_vec read; SH computed redundantly per lane (cheap ALU)
                const float* vp = edge_vec + (size_t)(eBase + e) * 3;
                float vx = vp[0], vy = vp[1], vz = vp[2];
                float rn = rsqrtf(vx * vx + vy * vy + vz * vz);
                float x = vx * rn, y = vy * rn, z = vz * rn;
                float sh1 = SQ3f * x, sh2 = SQ3f * y, sh3 = SQ3f * z;
                float sh4 = SQ15f * x * z;
                float sh5 = SQ15f * x * y;
                float sh6 = SQ5f  * (y * y - 0.5f * (x * x + z * z));
                float sh7 = SQ15f * y * z;
                float sh8 = (HSQ3f * SQ5f) * (z * z - x * x);

                float2 w0 = unpk(a0[e]), w1 = unpk(a1[e]), w2 = unpk(a2[e]);

                // stride-19 rows: odd stride -> conflict-free scalar STS
                float* sg = stage + s * 608 + lane * 19;
                sg[0]  = w0.x;
                sg[1]  = sh1 * w1.x; sg[2]  = sh2 * w1.x; sg[3]  = sh3 * w1.x;
                sg[4]  = sh4 * w2.x; sg[5]  = sh5 * w2.x; sg[6]  = sh6 * w2.x;
                sg[7]  = sh7 * w2.x; sg[8]  = sh8 * w2.x;
                sg[9]  = w0.y;
                sg[10] = sh1 * w1.y; sg[11] = sh2 * w1.y; sg[12] = sh3 * w1.y;
                sg[13] = sh4 * w2.y; sg[14] = sh5 * w2.y; sg[15] = sh6 * w2.y;
                sg[16] = sh7 * w2.y; sg[17] = sh8 * w2.y;
            }
            __syncwarp();

            // coalesced STG: 2 edges = 1152 floats = 288 float4 = 9 full warp rounds
            float4* op = (float4*)(out + (size_t)(eBase + ep) * 576);
            #pragma unroll
            for (int t = 0; t < 9; t++) {
                const int F0 = t * 128 + lane * 4;
                const int eo = (F0 >= 576) ? 1 : 0;   // float4 never crosses edge boundary
                float f[4];
                #pragma unroll
                for (int q = 0; q < 4; q++) {
                    int Fp = F0 + q - eo * 576;       // 0..575 within edge
                    int L  = Fp / 18;                 // owning lane row
                    int j  = Fp - L * 18;
                    f[q] = stage[eo * 608 + L * 19 + j];
                }
                op[t * 32 + lane] = make_float4(f[0], f[1], f[2], f[3]);
            }
            __syncwarp();
        }
    }
}

extern "C" void kernel_launch(void* const* d_in, const int* in_sizes, int n_in,
                              void* d_out, int out_size) {
    const float* edge_vec = (const float*)d_in[0];   // [E, 3]
    const float* inv      = (const float*)d_in[1];   // [E, 64]
    const float* W        = (const float*)d_in[2];   // [64, 192]
    float* out            = (float*)d_out;           // [E, 64, 9]
    (void)in_sizes; (void)n_in; (void)out_size;

    cudaFuncSetAttribute(sh_embed_kernel,
                         cudaFuncAttributeMaxDynamicSharedMemorySize, SMEM_BYTES);
    // 148 SMs x 3 blocks of 128 threads; grid-stride over 15625 16-edge tiles
    sh_embed_kernel<<<444, 128, SMEM_BYTES>>>(edge_vec, inv, W, out);
}

// round 4
// speedup vs baseline: 1.0561x; 1.0561x over previous
#include <cuda_runtime.h>
#include <cstdint>

static constexpr int E_EDGES = 250000;
static constexpr int T_E     = 16;                 // edges per warp tile
static constexpr int NTILE   = E_EDGES / T_E;      // 15625 (exact)

#define SQ3f  1.7320508075688772f
#define SQ5f  2.2360679774997896f
#define SQ15f 3.8729833462074170f
#define HSQ3f 0.8660254037844386f

typedef unsigned long long u64;

__device__ __forceinline__ u64 pack2(float a, float b) {
    u64 r; asm("mov.b64 %0, {%1, %2};" : "=l"(r) : "f"(a), "f"(b)); return r;
}
__device__ __forceinline__ float2 unpk(u64 v) {
    float2 r; asm("mov.b64 {%0, %1}, %2;" : "=f"(r.x), "=f"(r.y) : "l"(v)); return r;
}
__device__ __forceinline__ void fma2(u64& d, u64 a, u64 b) {
    asm("fma.rn.f32x2 %0, %1, %2, %0;" : "+l"(d) : "l"(a), "l"(b));
}

// Shared memory per block (128 threads = 4 warps):
//   WaS  : float4[64][32]                      32 KB (block-shared)
//   WbS  : float2[64][32]                      16 KB (block-shared)
//   invS : 4 warps x 16 edges x 64 floats      16 KB
//   stage: 4 warps x 2 edges x 608 floats      19 KB
static constexpr int WA_ELEMS       = 64 * 32;
static constexpr int INV_PER_WARP   = T_E * 64;     // 1024 floats
static constexpr int STAGE_PER_WARP = 2 * 608;      // floats
static constexpr int SMEM_BYTES     = WA_ELEMS * 16 + WA_ELEMS * 8
                                    + 4 * INV_PER_WARP * 4
                                    + 4 * STAGE_PER_WARP * 4;   // 84 KB

__global__ void __launch_bounds__(128, 2)
sh_embed_kernel(const float* __restrict__ edge_vec,
                const float* __restrict__ inv_g,
                const float* __restrict__ Wg,
                float* __restrict__ out)
{
    extern __shared__ char smem[];
    float4* WaS      = (float4*)smem;
    float2* WbS      = (float2*)(smem + WA_ELEMS * 16);
    float*  invS_all = (float*) (smem + WA_ELEMS * 16 + WA_ELEMS * 8);
    float*  stage_all= invS_all + 4 * INV_PER_WARP;

    const int tid  = threadIdx.x;
    const int lane = tid & 31;
    const int wid  = tid >> 5;
    float* invS  = invS_all  + wid * INV_PER_WARP;
    float* stage = stage_all + wid * STAGE_PER_WARP;

    // ---- repack W into per-lane channel-pair layout ----
    // lane cp owns channels c0=2cp, c1=2cp+1.
    // WaS[d][cp] = (W[d,6cp], W[d,6cp+3], W[d,6cp+1], W[d,6cp+4]) ; WbS[d][cp] = (W[d,6cp+2], W[d,6cp+5])
    for (int t = tid; t < WA_ELEMS; t += 128) {
        int cp = t & 31, d = t >> 5;
        const float* wr = Wg + d * 192 + cp * 6;
        WaS[t] = make_float4(wr[0], wr[3], wr[1], wr[4]);
        WbS[t] = make_float2(wr[2], wr[5]);
    }
    __syncthreads();

    const int warpsTotal = gridDim.x * 4;
    #pragma unroll 1
    for (int tile = blockIdx.x * 4 + wid; tile < NTILE; tile += warpsTotal) {
        const int eBase = tile * T_E;

        // ---- stage inv tile (16 edges x 64 floats = 256 float4) into smem, coalesced ----
        {
            const float4* src = (const float4*)(inv_g + (size_t)eBase * 64);
            float4*       dst = (float4*)invS;
            #pragma unroll
            for (int r = 0; r < 8; r++)
                dst[r * 32 + lane] = src[r * 32 + lane];
        }
        __syncwarp();

        // accumulators: per edge, f32x2 over (c0,c1), one per irrep
        u64 a0[T_E], a1[T_E], a2[T_E];
        #pragma unroll
        for (int e = 0; e < T_E; e++) { a0[e] = 0; a1[e] = 0; a2[e] = 0; }

        // ---- GEMM: w[e, c, i] = sum_d inv[e,d] * W[d, c*3+i] ----
        #pragma unroll 1
        for (int d4 = 0; d4 < 16; ++d4) {
            // this lane's W columns for 4 d-rows (per-lane distinct, full-width LDS)
            u64 A0[4], A1[4], A2[4];
            #pragma unroll
            for (int dd = 0; dd < 4; ++dd) {
                float4 wa = WaS[(d4 * 4 + dd) * 32 + lane];
                float2 wb = WbS[(d4 * 4 + dd) * 32 + lane];
                A0[dd] = pack2(wa.x, wa.y);
                A1[dd] = pack2(wa.z, wa.w);
                A2[dd] = pack2(wb.x, wb.y);
            }
            #pragma unroll
            for (int e = 0; e < T_E; e++) {
                // warp-uniform LDS.128 broadcast: 1 wavefront, 29-cyc latency
                float4 iv = *(const float4*)(invS + e * 64 + d4 * 4);
                u64 i0 = pack2(iv.x, iv.x);
                u64 i1 = pack2(iv.y, iv.y);
                u64 i2 = pack2(iv.z, iv.z);
                u64 i3 = pack2(iv.w, iv.w);
                fma2(a0[e], i0, A0[0]); fma2(a1[e], i0, A1[0]); fma2(a2[e], i0, A2[0]);
                fma2(a0[e], i1, A0[1]); fma2(a1[e], i1, A1[1]); fma2(a2[e], i1, A2[1]);
                fma2(a0[e], i2, A0[2]); fma2(a1[e], i2, A1[2]); fma2(a2[e], i2, A2[2]);
                fma2(a0[e], i3, A0[3]); fma2(a1[e], i3, A1[3]); fma2(a2[e], i3, A2[3]);
            }
        }

        // ---- epilogue: SH outer product + transpose-through-smem, 2 edges per pass ----
        #pragma unroll 1
        for (int ep = 0; ep < T_E; ep += 2) {
            #pragma unroll
            for (int s = 0; s < 2; ++s) {
                const int e = ep + s;
                const float* vp = edge_vec + (size_t)(eBase + e) * 3;
                float vx = vp[0], vy = vp[1], vz = vp[2];
                float rn = rsqrtf(vx * vx + vy * vy + vz * vz);
                float x = vx * rn, y = vy * rn, z = vz * rn;
                float sh1 = SQ3f * x, sh2 = SQ3f * y, sh3 = SQ3f * z;
                float sh4 = SQ15f * x * z;
                float sh5 = SQ15f * x * y;
                float sh6 = SQ5f  * (y * y - 0.5f * (x * x + z * z));
                float sh7 = SQ15f * y * z;
                float sh8 = (HSQ3f * SQ5f) * (z * z - x * x);

                float2 w0 = unpk(a0[e]), w1 = unpk(a1[e]), w2 = unpk(a2[e]);

                // stride-19 rows: odd stride -> conflict-free scalar STS
                float* sg = stage + s * 608 + lane * 19;
                sg[0]  = w0.x;
                sg[1]  = sh1 * w1.x; sg[2]  = sh2 * w1.x; sg[3]  = sh3 * w1.x;
                sg[4]  = sh4 * w2.x; sg[5]  = sh5 * w2.x; sg[6]  = sh6 * w2.x;
                sg[7]  = sh7 * w2.x; sg[8]  = sh8 * w2.x;
                sg[9]  = w0.y;
                sg[10] = sh1 * w1.y; sg[11] = sh2 * w1.y; sg[12] = sh3 * w1.y;
                sg[13] = sh4 * w2.y; sg[14] = sh5 * w2.y; sg[15] = sh6 * w2.y;
                sg[16] = sh7 * w2.y; sg[17] = sh8 * w2.y;
            }
            __syncwarp();

            // coalesced STG: 2 edges = 1152 floats = 288 float4 = 9 full warp rounds
            float4* op = (float4*)(out + (size_t)(eBase + ep) * 576);
            #pragma unroll
            for (int t = 0; t < 9; t++) {
                const int F0 = t * 128 + lane * 4;
                const int eo = (F0 >= 576) ? 1 : 0;   // float4 never crosses edge boundary
                float f[4];
                #pragma unroll
                for (int q = 0; q < 4; q++) {
                    int Fp = F0 + q - eo * 576;       // 0..575 within edge
                    int L  = Fp / 18;                 // owning lane row
                    int j  = Fp - L * 18;
                    f[q] = stage[eo * 608 + L * 19 + j];
                }
                op[t * 32 + lane] = make_float4(f[0], f[1], f[2], f[3]);
            }
            __syncwarp();
        }
    }
}

extern "C" void kernel_launch(void* const* d_in, const int* in_sizes, int n_in,
                              void* d_out, int out_size) {
    const float* edge_vec = (const float*)d_in[0];   // [E, 3]
    const float* inv      = (const float*)d_in[1];   // [E, 64]
    const float* W        = (const float*)d_in[2];   // [64, 192]
    float* out            = (float*)d_out;           // [E, 64, 9]
    (void)in_sizes; (void)n_in; (void)out_size;

    cudaFuncSetAttribute(sh_embed_kernel,
                         cudaFuncAttributeMaxDynamicSharedMemorySize, SMEM_BYTES);
    // 296 blocks (2/SM, 84KB smem each), 4 warps/block; grid-stride over 15625 tiles
    sh_embed_kernel<<<296, 128, SMEM_BYTES>>>(edge_vec, inv, W, out);
}

// round 5
// speedup vs baseline: 2.9100x; 2.7553x over previous
#include <cuda_runtime.h>
#include <cstdint>

static constexpr int E_EDGES = 250000;
static constexpr int T_E     = 8;                  // edges per warp tile
static constexpr int NTILE   = E_EDGES / T_E;      // 31250 (exact)

#define SQ3f  1.7320508075688772f
#define SQ5f  2.2360679774997896f
#define SQ15f 3.8729833462074170f
#define HSQ3f 0.8660254037844386f

typedef unsigned long long u64;

__device__ __forceinline__ u64 pack2(float a, float b) {
    u64 r; asm("mov.b64 %0, {%1, %2};" : "=l"(r) : "f"(a), "f"(b)); return r;
}
__device__ __forceinline__ float2 unpk(u64 v) {
    float2 r; asm("mov.b64 {%0, %1}, %2;" : "=f"(r.x), "=f"(r.y) : "l"(v)); return r;
}
__device__ __forceinline__ void fma2(u64& d, u64 a, u64 b) {
    asm("fma.rn.f32x2 %0, %1, %2, %0;" : "+l"(d) : "l"(a), "l"(b));
}

// ---- shared memory layout per 256-thread block (8 warps) ----
//  WaS  : float4[64][32]                          32768 B  (block-shared)
//  WbS  : float2[64][32]                          16384 B  (block-shared)
//  invS : 8 warps x (8 edges x 64 f)              16384 B
//  shS  : 8 warps x (8 edges x 2 float4)           2048 B  (precomputed SH)
//  stage: 8 warps x 2 slots x 292 float2          37376 B
static constexpr int OFF_WB    = 32768;
static constexpr int OFF_INV   = 49152;
static constexpr int OFF_SH    = 65536;
static constexpr int OFF_STAGE = 67584;
static constexpr int SMEM_BYTES = 104960;
static constexpr int STAGE_SLOT_B = 2336;          // 292 float2, 16B-aligned
static constexpr int STAGE_WARP_B = 2 * STAGE_SLOT_B;

__global__ void __launch_bounds__(256, 2)
sh_embed_kernel(const float* __restrict__ edge_vec,
                const float* __restrict__ inv_g,
                const float* __restrict__ Wg,
                float* __restrict__ out)
{
    extern __shared__ char smem[];
    float4* WaS   = (float4*)smem;
    float2* WbS   = (float2*)(smem + OFF_WB);

    const int tid  = threadIdx.x;
    const int lane = tid & 31;
    const int wid  = tid >> 5;

    float*  invS   = (float*) (smem + OFF_INV)   + wid * (T_E * 64);
    float4* shS4   = (float4*)(smem + OFF_SH)    + wid * (T_E * 2);
    char*   stageB = smem + OFF_STAGE + wid * STAGE_WARP_B;
    float2* stageF2= (float2*)stageB;

    // ---- repack W: lane cp owns channels c0=2cp, c1=2cp+1 ----
    // WaS[d][cp]=(W[d,6cp],W[d,6cp+3],W[d,6cp+1],W[d,6cp+4]); WbS[d][cp]=(W[d,6cp+2],W[d,6cp+5])
    for (int t = tid; t < 64 * 32; t += 256) {
        int cp = t & 31, d = t >> 5;
        const float* wr = Wg + d * 192 + cp * 6;
        WaS[t] = make_float4(wr[0], wr[3], wr[1], wr[4]);
        WbS[t] = make_float2(wr[2], wr[5]);
    }
    __syncthreads();

    const int warpsTotal = gridDim.x * 8;
    #pragma unroll 1
    for (int tile = blockIdx.x * 8 + wid; tile < NTILE; tile += warpsTotal) {
        const int eBase = tile * T_E;

        // ---- stage inv tile (8 edges x 64 f = 128 float4), coalesced ----
        {
            const float4* src = (const float4*)(inv_g + (size_t)eBase * 64);
            float4*       dst = (float4*)invS;
            #pragma unroll
            for (int r = 0; r < 4; r++)
                dst[r * 32 + lane] = src[r * 32 + lane];
        }

        // ---- precompute SH for the 8 edges (lanes 0..7, one edge each) ----
        if (lane < T_E) {
            const float* vp = edge_vec + (size_t)(eBase + lane) * 3;
            float vx = vp[0], vy = vp[1], vz = vp[2];
            float rn = rsqrtf(vx * vx + vy * vy + vz * vz);
            float x = vx * rn, y = vy * rn, z = vz * rn;
            shS4[lane * 2 + 0] = make_float4(SQ3f * x, SQ3f * y, SQ3f * z, SQ15f * x * z);
            shS4[lane * 2 + 1] = make_float4(SQ15f * x * y,
                                             SQ5f  * (y * y - 0.5f * (x * x + z * z)),
                                             SQ15f * y * z,
                                             (HSQ3f * SQ5f) * (z * z - x * x));
        }
        __syncwarp();

        // ---- GEMM: w[e, c, i] = sum_d inv[e,d] * W[d, c*3+i] ----
        u64 a0[T_E], a1[T_E], a2[T_E];
        #pragma unroll
        for (int e = 0; e < T_E; e++) { a0[e] = 0; a1[e] = 0; a2[e] = 0; }

        #pragma unroll 1
        for (int d4 = 0; d4 < 16; ++d4) {
            u64 A0[4], A1[4], A2[4];
            #pragma unroll
            for (int dd = 0; dd < 4; ++dd) {
                float4 wa = WaS[(d4 * 4 + dd) * 32 + lane];
                float2 wb = WbS[(d4 * 4 + dd) * 32 + lane];
                A0[dd] = pack2(wa.x, wa.y);
                A1[dd] = pack2(wa.z, wa.w);
                A2[dd] = pack2(wb.x, wb.y);
            }
            #pragma unroll
            for (int e = 0; e < T_E; e++) {
                float4 iv = *(const float4*)(invS + e * 64 + d4 * 4);   // uniform LDS.128
                u64 i0 = pack2(iv.x, iv.x);
                u64 i1 = pack2(iv.y, iv.y);
                u64 i2 = pack2(iv.z, iv.z);
                u64 i3 = pack2(iv.w, iv.w);
                fma2(a0[e], i0, A0[0]); fma2(a1[e], i0, A1[0]); fma2(a2[e], i0, A2[0]);
                fma2(a0[e], i1, A0[1]); fma2(a1[e], i1, A1[1]); fma2(a2[e], i1, A2[1]);
                fma2(a0[e], i2, A0[2]); fma2(a1[e], i2, A1[2]); fma2(a2[e], i2, A2[2]);
                fma2(a0[e], i3, A0[3]); fma2(a1[e], i3, A1[3]); fma2(a2[e], i3, A2[3]);
            }
        }

        // ---- epilogue: 2 edges per pass, float2 staging + wide readback ----
        // lane cp's float2 slot j lives at idx2 = 9*cp + 2*(cp>>4) + j  (pad kills
        // the (cp, cp+16) bank tie; 16B hole at idx 144/145 keeps alignment)
        const int sBase = lane * 9 + 2 * (lane >> 4);
        #pragma unroll 1
        for (int ep = 0; ep < T_E; ep += 2) {
            #pragma unroll
            for (int s = 0; s < 2; ++s) {
                const int e = ep + s;
                float4 shA = shS4[e * 2 + 0];   // sh1..sh4
                float4 shB = shS4[e * 2 + 1];   // sh5..sh8
                float2 w0 = unpk(a0[e]), w1 = unpk(a1[e]), w2 = unpk(a2[e]);
                float2* sg = stageF2 + s * 292 + sBase;
                sg[0] = make_float2(w0.x,        shA.x * w1.x);
                sg[1] = make_float2(shA.y * w1.x, shA.z * w1.x);
                sg[2] = make_float2(shA.w * w2.x, shB.x * w2.x);
                sg[3] = make_float2(shB.y * w2.x, shB.z * w2.x);
                sg[4] = make_float2(shB.w * w2.x, w0.y);
                sg[5] = make_float2(shA.x * w1.y, shA.y * w1.y);
                sg[6] = make_float2(shA.z * w1.y, shA.w * w2.y);
                sg[7] = make_float2(shB.x * w2.y, shB.y * w2.y);
                sg[8] = make_float2(shB.z * w2.y, shB.w * w2.y);
            }
            __syncwarp();

            // 2 edges = 288 float4 contiguous in out; 9 full warp rounds
            float4* op = (float4*)(out + (size_t)(eBase + ep) * 576);
            #pragma unroll
            for (int t = 0; t < 9; t++) {
                int r  = t * 32 + lane;            // 0..287
                int eo = (r >= 144) ? 1 : 0;
                int rr = r - eo * 144;             // 0..143 within edge
                int byte = eo * STAGE_SLOT_B + rr * 16 + ((rr >= 72) ? 16 : 0);
                float4 v = *(const float4*)(stageB + byte);
                op[r] = v;
            }
            __syncwarp();
        }
    }
}

extern "C" void kernel_launch(void* const* d_in, const int* in_sizes, int n_in,
                              void* d_out, int out_size) {
    const float* edge_vec = (const float*)d_in[0];   // [E, 3]
    const float* inv      = (const float*)d_in[1];   // [E, 64]
    const float* W        = (const float*)d_in[2];   // [64, 192]
    float* out            = (float*)d_out;           // [E, 64, 9]
    (void)in_sizes; (void)n_in; (void)out_size;

    cudaFuncSetAttribute(sh_embed_kernel,
                         cudaFuncAttributeMaxDynamicSharedMemorySize, SMEM_BYTES);
    // 296 blocks (2/SM at 105KB smem), 8 warps each = 16 warps/SM;
    // grid-stride over 31250 8-edge tiles
    sh_embed_kernel<<<296, 256, SMEM_BYTES>>>(edge_vec, inv, W, out);
}

// round 6
// speedup vs baseline: 2.9902x; 1.0276x over previous
#include <cuda_runtime.h>
#include <cstdint>

static constexpr int E_EDGES = 250000;
static constexpr int T_E     = 8;                  // edges per warp tile
static constexpr int NTILE   = E_EDGES / T_E;      // 31250 (exact)

#define SQ3f  1.7320508075688772f
#define SQ5f  2.2360679774997896f
#define SQ15f 3.8729833462074170f
#define HSQ3f 0.8660254037844386f

typedef unsigned long long u64;

__device__ __forceinline__ u64 pack2(float a, float b) {
    u64 r; asm("mov.b64 %0, {%1, %2};" : "=l"(r) : "f"(a), "f"(b)); return r;
}
__device__ __forceinline__ float2 unpk(u64 v) {
    float2 r; asm("mov.b64 {%0, %1}, %2;" : "=f"(r.x), "=f"(r.y) : "l"(v)); return r;
}
__device__ __forceinline__ void fma2(u64& d, u64 a, u64 b) {
    asm("fma.rn.f32x2 %0, %1, %2, %0;" : "+l"(d) : "l"(a), "l"(b));
}
__device__ __forceinline__ uint32_t smem_u32(const void* p) {
    uint32_t a;
    asm("{ .reg .u64 t; cvta.to.shared.u64 t, %1; cvt.u32.u64 %0, t; }" : "=r"(a) : "l"(p));
    return a;
}

// ---- shared memory layout per 256-thread block (8 warps) ----
//  WaS  : float4[64][32]                          32768 B  (block-shared)
//  WbS  : float2[64][32]                          16384 B
//  invS : 8 warps x (8 edges x 64 f)              16384 B
//  shS  : 8 warps x (8 edges x 2 float4)           2048 B
//  stage: 8 warps x 2 slots x 2304 B              36864 B  (TMA store staging)
static constexpr int OFF_WB    = 32768;
static constexpr int OFF_INV   = 49152;
static constexpr int OFF_SH    = 65536;
static constexpr int OFF_STAGE = 67584;
static constexpr int SMEM_BYTES = 104448;
static constexpr int EDGE_BYTES = 576 * 4;         // 2304, 16B multiple

__global__ void __launch_bounds__(256, 2)
sh_embed_kernel(const float* __restrict__ edge_vec,
                const float* __restrict__ inv_g,
                const float* __restrict__ Wg,
                float* __restrict__ out)
{
    extern __shared__ char smem[];
    float4* WaS = (float4*)smem;
    float2* WbS = (float2*)(smem + OFF_WB);

    const int tid  = threadIdx.x;
    const int lane = tid & 31;
    const int wid  = tid >> 5;

    float*  invS   = (float*) (smem + OFF_INV) + wid * (T_E * 64);
    float4* shS4   = (float4*)(smem + OFF_SH)  + wid * (T_E * 2);
    char*   stageB = smem + OFF_STAGE + wid * (2 * EDGE_BYTES);
    const uint32_t stageAddr = smem_u32(stageB);

    // ---- repack W: lane cp owns channels c0=2cp, c1=2cp+1 ----
    for (int t = tid; t < 64 * 32; t += 256) {
        int cp = t & 31, d = t >> 5;
        const float* wr = Wg + d * 192 + cp * 6;
        WaS[t] = make_float4(wr[0], wr[3], wr[1], wr[4]);
        WbS[t] = make_float2(wr[2], wr[5]);
    }
    __syncthreads();

    const int warpsTotal = gridDim.x * 8;
    #pragma unroll 1
    for (int tile = blockIdx.x * 8 + wid; tile < NTILE; tile += warpsTotal) {
        const int eBase = tile * T_E;

        // ---- stage inv tile (8 edges x 64 f = 128 float4), coalesced ----
        {
            const float4* src = (const float4*)(inv_g + (size_t)eBase * 64);
            float4*       dst = (float4*)invS;
            #pragma unroll
            for (int r = 0; r < 4; r++)
                dst[r * 32 + lane] = src[r * 32 + lane];
        }

        // ---- precompute SH for the 8 edges (lanes 0..7) ----
        if (lane < T_E) {
            const float* vp = edge_vec + (size_t)(eBase + lane) * 3;
            float vx = vp[0], vy = vp[1], vz = vp[2];
            float rn = rsqrtf(vx * vx + vy * vy + vz * vz);
            float x = vx * rn, y = vy * rn, z = vz * rn;
            shS4[lane * 2 + 0] = make_float4(SQ3f * x, SQ3f * y, SQ3f * z, SQ15f * x * z);
            shS4[lane * 2 + 1] = make_float4(SQ15f * x * y,
                                             SQ5f  * (y * y - 0.5f * (x * x + z * z)),
                                             SQ15f * y * z,
                                             (HSQ3f * SQ5f) * (z * z - x * x));
        }
        __syncwarp();

        // ---- GEMM: w[e, c, i] = sum_d inv[e,d] * W[d, c*3+i] ----
        u64 a0[T_E], a1[T_E], a2[T_E];
        #pragma unroll
        for (int e = 0; e < T_E; e++) { a0[e] = 0; a1[e] = 0; a2[e] = 0; }

        #pragma unroll 1
        for (int d4 = 0; d4 < 16; ++d4) {
            u64 A0[4], A1[4], A2[4];
            #pragma unroll
            for (int dd = 0; dd < 4; ++dd) {
                float4 wa = WaS[(d4 * 4 + dd) * 32 + lane];
                float2 wb = WbS[(d4 * 4 + dd) * 32 + lane];
                A0[dd] = pack2(wa.x, wa.y);
                A1[dd] = pack2(wa.z, wa.w);
                A2[dd] = pack2(wb.x, wb.y);
            }
            #pragma unroll
            for (int e = 0; e < T_E; e++) {
                float4 iv = *(const float4*)(invS + e * 64 + d4 * 4);   // uniform LDS.128
                u64 i0 = pack2(iv.x, iv.x);
                u64 i1 = pack2(iv.y, iv.y);
                u64 i2 = pack2(iv.z, iv.z);
                u64 i3 = pack2(iv.w, iv.w);
                fma2(a0[e], i0, A0[0]); fma2(a1[e], i0, A1[0]); fma2(a2[e], i0, A2[0]);
                fma2(a0[e], i1, A0[1]); fma2(a1[e], i1, A1[1]); fma2(a2[e], i1, A2[1]);
                fma2(a0[e], i2, A0[2]); fma2(a1[e], i2, A1[2]); fma2(a2[e], i2, A2[2]);
                fma2(a0[e], i3, A0[3]); fma2(a1[e], i3, A1[3]); fma2(a2[e], i3, A2[3]);
            }
        }

        // ---- epilogue: stage each edge in FINAL layout, TMA bulk store it ----
        // lane cp's 18 floats are contiguous at float offset 18*cp.
        const int rot = lane >> 4;   // lanes 16..31 rotate write order by 1 (bank de-tie)
        #pragma unroll 1
        for (int e = 0; e < T_E; ++e) {
            // slot reuse guard: the store issued 2 edges ago must have drained
            if (lane == 0) asm volatile("cp.async.bulk.wait_group 1;" ::: "memory");
            __syncwarp();

            float4 shA = shS4[e * 2 + 0];   // sh1..sh4
            float4 shB = shS4[e * 2 + 1];   // sh5..sh8
            float2 w0 = unpk(a0[e]), w1 = unpk(a1[e]), w2 = unpk(a2[e]);

            float2 pr[9];
            pr[0] = make_float2(w0.x,         shA.x * w1.x);
            pr[1] = make_float2(shA.y * w1.x, shA.z * w1.x);
            pr[2] = make_float2(shA.w * w2.x, shB.x * w2.x);
            pr[3] = make_float2(shB.y * w2.x, shB.z * w2.x);
            pr[4] = make_float2(shB.w * w2.x, w0.y);
            pr[5] = make_float2(shA.x * w1.y, shA.y * w1.y);
            pr[6] = make_float2(shA.z * w1.y, shA.w * w2.y);
            pr[7] = make_float2(shB.x * w2.y, shB.y * w2.y);
            pr[8] = make_float2(shB.z * w2.y, shB.w * w2.y);

            float2* sp = (float2*)(stageB + (e & 1) * EDGE_BYTES) + lane * 9;
            #pragma unroll
            for (int m = 0; m < 9; m++) {
                const int k = (m + 1) % 9;            // compile-time
                float2 v  = rot ? pr[k] : pr[m];      // constant-indexed selects
                int    o  = rot ? k     : m;
                sp[o] = v;
            }
            __syncwarp();

            if (lane == 0) {
                asm volatile("fence.proxy.async.shared::cta;" ::: "memory");
                const float* gdst = out + (size_t)(eBase + e) * 576;
                uint32_t saddr = stageAddr + (e & 1) * EDGE_BYTES;
                asm volatile(
                    "cp.async.bulk.global.shared::cta.bulk_group [%0], [%1], %2;"
                    :: "l"(gdst), "r"(saddr), "n"(EDGE_BYTES) : "memory");
                asm volatile("cp.async.bulk.commit_group;" ::: "memory");
            }
            __syncwarp();
        }
    }

    // all of this warp's TMA stores must drain before smem can be released
    if (lane == 0) asm volatile("cp.async.bulk.wait_group 0;" ::: "memory");
    __syncwarp();
}

extern "C" void kernel_launch(void* const* d_in, const int* in_sizes, int n_in,
                              void* d_out, int out_size) {
    const float* edge_vec = (const float*)d_in[0];   // [E, 3]
    const float* inv      = (const float*)d_in[1];   // [E, 64]
    const float* W        = (const float*)d_in[2];   // [64, 192]
    float* out            = (float*)d_out;           // [E, 64, 9]
    (void)in_sizes; (void)n_in; (void)out_size;

    cudaFuncSetAttribute(sh_embed_kernel,
                         cudaFuncAttributeMaxDynamicSharedMemorySize, SMEM_BYTES);
    // 296 blocks (2/SM at 102KB smem), 8 warps each = 16 warps/SM
    sh_embed_kernel<<<296, 256, SMEM_BYTES>>>(edge_vec, inv, W, out);
}